// round 5
// baseline (speedup 1.0000x reference)
#include <cuda_runtime.h>
#include <math.h>
#include <stdint.h>

// ---------------- problem constants ----------------
#define M_TOT   12288
#define K1      768
#define H_DIM   3072
#define N_SHARED 512
#define N_PART  256
#define D_OUT   768
#define S_LEN   192
#define B_TOT   64

// element counts
#define N_X   ((size_t)M_TOT * K1)        // 9437184
#define N_W1  ((size_t)H_DIM * K1)        // 2359296
#define N_W2  ((size_t)N_SHARED * H_DIM)  // 1572864
#define N_EW  ((size_t)6 * N_PART * H_DIM)// 4718592

// ---------------- tiling ----------------
#define BK 32
#define TST 36                         // smem row stride in floats (144B, 16B-aligned, conflict-free)
#define TILE_F  (128 * TST)            // 4608 floats per operand tile
#define STAGE_F (2 * TILE_F)           // 9216
#define SMEM_BYTES (3 * STAGE_F * 4)   // 110592 (3 stages)

// ---------------- device scratch (tf32-pre-rounded copies) ----------------
static __device__ float g_h [(size_t)M_TOT * H_DIM];
static __device__ float g_x [N_X];
static __device__ float g_w1[N_W1];
static __device__ float g_w2[N_W2];
static __device__ float g_ew[N_EW];
static __device__ int   g_idx[B_TOT];

// ---------------- helpers ----------------
__device__ __forceinline__ float to_tf32(float x) {
    float r; asm("cvt.rna.tf32.f32 %0, %1;" : "=f"(r) : "f"(x)); return r;
}
__device__ __forceinline__ float gelu_erf(float x) {
    return 0.5f * x * (1.0f + erff(x * 0.70710678118654752440f));
}
__device__ __forceinline__ void mma_tf32(float* c, const uint32_t* a, const uint32_t* b) {
    asm volatile(
        "mma.sync.aligned.m16n8k8.row.col.f32.tf32.tf32.f32 "
        "{%0,%1,%2,%3}, {%4,%5,%6,%7}, {%8,%9}, {%0,%1,%2,%3};"
        : "+f"(c[0]), "+f"(c[1]), "+f"(c[2]), "+f"(c[3])
        : "r"(a[0]), "r"(a[1]), "r"(a[2]), "r"(a[3]), "r"(b[0]), "r"(b[1]));
}
__device__ __forceinline__ uint32_t smem_u32(const void* p) {
    uint32_t a;
    asm("{ .reg .u64 t; cvta.to.shared.u64 t, %1; cvt.u32.u64 %0, t; }" : "=r"(a) : "l"(p));
    return a;
}
__device__ __forceinline__ void cp16(uint32_t dst, const float* src) {
    asm volatile("cp.async.cg.shared.global [%0], [%1], 16;" :: "r"(dst), "l"(src));
}
__device__ __forceinline__ void cp_commit() {
    asm volatile("cp.async.commit_group;" ::: "memory");
}

// ---------------- prep: tf32-round inputs + decode indices ----------------
__global__ void prep_kernel(const float* __restrict__ X,
                            const float* __restrict__ w1,
                            const float* __restrict__ w2,
                            const float* __restrict__ ew,
                            const int*   __restrict__ raw)
{
    if (blockIdx.x == 0 && threadIdx.x == 0) {
        int odd_or = 0;
        for (int i = 1; i < B_TOT; i += 2) odd_or |= raw[i];
        const int is64 = (odd_or == 0);
        for (int b = 0; b < B_TOT; b++) g_idx[b] = is64 ? raw[2 * b] : raw[b];
    }
    const size_t total4 = (N_X + N_W1 + N_W2 + N_EW) / 4;
    const size_t b1 = N_X / 4, b2 = b1 + N_W1 / 4, b3 = b2 + N_W2 / 4;
    for (size_t i = (size_t)blockIdx.x * blockDim.x + threadIdx.x; i < total4;
         i += (size_t)gridDim.x * blockDim.x) {
        const float4* src; float4* dst; size_t o;
        if (i < b1)      { src = (const float4*)X;  dst = (float4*)g_x;  o = i; }
        else if (i < b2) { src = (const float4*)w1; dst = (float4*)g_w1; o = i - b1; }
        else if (i < b3) { src = (const float4*)w2; dst = (float4*)g_w2; o = i - b2; }
        else             { src = (const float4*)ew; dst = (float4*)g_ew; o = i - b3; }
        float4 v = src[o];
        v.x = to_tf32(v.x); v.y = to_tf32(v.y); v.z = to_tf32(v.z); v.w = to_tf32(v.w);
        dst[o] = v;
    }
}

// ---------------- tf32 GEMM: D[128,128] = A[128,K] @ B[128,K]^T (+bias, opt GELU/round) ----
// Inputs already tf32-rounded. 128 threads, 4 warps 2(M)x2(N), warp tile 64x64.
// 3-stage cp.async pipeline, smem row stride 36 floats (bank = lane+kb, conflict-free).
template <bool GELU>
__device__ __forceinline__ void gemm_tf32(
    const float* __restrict__ A, int ldA,
    const float* __restrict__ B, int ldB,
    int NS,
    float* __restrict__ out, int ldOut,
    const float* __restrict__ bias)
{
    extern __shared__ float sm[];
    const uint32_t sb = smem_u32(sm);
    const int tid  = threadIdx.x;
    const int lane = tid & 31;
    const int wid  = tid >> 5;
    const int g = lane >> 2;
    const int t = lane & 3;
    const int wm = (wid & 1) * 64;
    const int wn = (wid >> 1) * 64;

    float acc[4][8][4];
#pragma unroll
    for (int mt = 0; mt < 4; mt++)
#pragma unroll
        for (int nt = 0; nt < 8; nt++)
#pragma unroll
            for (int q = 0; q < 4; q++) acc[mt][nt][q] = 0.f;

    // per-thread cp.async source/dest: thread tid copies smem row tid (8 x 16B per operand)
    const float* Ag = A + (size_t)tid * ldA;
    const float* Bg = B + (size_t)tid * ldB;
    const uint32_t sa0 = sb + (uint32_t)tid * 144u;               // + stage*STAGE_F*4
    const uint32_t sb0 = sb + (uint32_t)(TILE_F * 4) + (uint32_t)tid * 144u;

    // prologue: stages 0,1
#pragma unroll
    for (int s = 0; s < 2; s++) {
        const int k0 = s * BK;
        const uint32_t so = (uint32_t)(s * STAGE_F * 4);
#pragma unroll
        for (int j = 0; j < 8; j++) cp16(sa0 + so + j * 16u, Ag + k0 + j * 4);
#pragma unroll
        for (int j = 0; j < 8; j++) cp16(sb0 + so + j * 16u, Bg + k0 + j * 4);
        cp_commit();
    }

    int st = 0;  // stage buffer index of s
    for (int s = 0; s < NS; s++) {
        if (s + 2 < NS) asm volatile("cp.async.wait_group 1;" ::: "memory");
        else            asm volatile("cp.async.wait_group 0;" ::: "memory");
        __syncthreads();

        const float* as = sm + st * STAGE_F + wm * TST;
        const float* bs = sm + st * STAGE_F + TILE_F + wn * TST;
#pragma unroll
        for (int kb = 0; kb < BK; kb += 8) {
            uint32_t af[4][4];
#pragma unroll
            for (int mt = 0; mt < 4; mt++) {
                const int base = (mt * 16 + g) * TST + kb + t;
                af[mt][0] = __float_as_uint(as[base]);
                af[mt][1] = __float_as_uint(as[base + 8 * TST]);
                af[mt][2] = __float_as_uint(as[base + 4]);
                af[mt][3] = __float_as_uint(as[base + 8 * TST + 4]);
            }
            uint32_t bf[8][2];
#pragma unroll
            for (int nt = 0; nt < 8; nt++) {
                const int base = (nt * 8 + g) * TST + kb + t;
                bf[nt][0] = __float_as_uint(bs[base]);
                bf[nt][1] = __float_as_uint(bs[base + 4]);
            }
#pragma unroll
            for (int mt = 0; mt < 4; mt++)
#pragma unroll
                for (int nt = 0; nt < 8; nt++)
                    mma_tf32(acc[mt][nt], af[mt], bf[nt]);
        }

        // issue stage s+2 into the buffer freed at the sync above
        if (s + 2 < NS) {
            const int k0 = (s + 2) * BK;
            const int st2 = (st + 2 >= 3) ? st - 1 : st + 2;
            const uint32_t so = (uint32_t)(st2 * STAGE_F * 4);
#pragma unroll
            for (int j = 0; j < 8; j++) cp16(sa0 + so + j * 16u, Ag + k0 + j * 4);
#pragma unroll
            for (int j = 0; j < 8; j++) cp16(sb0 + so + j * 16u, Bg + k0 + j * 4);
            cp_commit();
        }
        st = (st + 1 == 3) ? 0 : st + 1;
    }

    // epilogue: bias (+GELU+tf32-round), float2 stores
#pragma unroll
    for (int nt = 0; nt < 8; nt++) {
        const int col = wn + nt * 8 + 2 * t;
        const float2 bv = *(const float2*)(bias + col);
#pragma unroll
        for (int mt = 0; mt < 4; mt++) {
            const int r = wm + mt * 16 + g;
            float2 v0, v1;
            v0.x = acc[mt][nt][0] + bv.x; v0.y = acc[mt][nt][1] + bv.y;
            v1.x = acc[mt][nt][2] + bv.x; v1.y = acc[mt][nt][3] + bv.y;
            if (GELU) {
                v0.x = to_tf32(gelu_erf(v0.x)); v0.y = to_tf32(gelu_erf(v0.y));
                v1.x = to_tf32(gelu_erf(v1.x)); v1.y = to_tf32(gelu_erf(v1.y));
            }
            *(float2*)(out + (size_t)r * ldOut + col) = v0;
            *(float2*)(out + (size_t)(r + 8) * ldOut + col) = v1;
        }
    }
}

// ---------------- kernel 1: g_h = tf32(gelu(X @ fc1_w^T + b)) ----------------
__global__ void __launch_bounds__(128, 2) fc1_kernel(const float* __restrict__ bias)
{
    const int bm = blockIdx.y * 128;
    const int bn = blockIdx.x * 128;
    gemm_tf32<true>(g_x + (size_t)bm * K1, K1,
                    g_w1 + (size_t)bn * K1, K1, K1 / BK,
                    g_h + (size_t)bm * H_DIM + bn, H_DIM, bias + bn);
}

// ---------------- kernel 2: fused shared fc2 + expert ----------------
__global__ void __launch_bounds__(128, 2) fc2_kernel(
    const float* __restrict__ fc2_b,
    const float* __restrict__ eb,
    float* __restrict__ out)
{
    const int job = blockIdx.x;
    int bm, outcol;
    const float* Bb;
    const float* bp;
    if (job < 384) {
        const int m = job >> 2, n = job & 3;
        bm = m * 128;
        outcol = n * 128;
        Bb = g_w2 + (size_t)outcol * H_DIM;
        bp = fc2_b + outcol;
    } else {
        const int j = job - 384;
        const int b = j >> 2, mt = (j >> 1) & 1, nt = j & 1;
        bm = b * S_LEN + mt * 64;            // overlapping M=128 tiles write identical bytes
        const int nb = nt * 128;
        const int e = g_idx[b];
        Bb = g_ew + ((size_t)e * N_PART + nb) * H_DIM;
        bp = eb + (size_t)e * N_PART + nb;
        outcol = N_SHARED + nb;
    }
    gemm_tf32<false>(g_h + (size_t)bm * H_DIM, H_DIM,
                     Bb, H_DIM, H_DIM / BK,
                     out + (size_t)bm * D_OUT + outcol, D_OUT, bp);
}

// ---------------- launch ----------------
extern "C" void kernel_launch(void* const* d_in, const int* in_sizes, int n_in,
                              void* d_out, int out_size)
{
    (void)in_sizes; (void)n_in; (void)out_size;
    const float* hs    = (const float*)d_in[0];
    const int*   raw   = (const int*)d_in[1];
    const float* fc1_w = (const float*)d_in[2];
    const float* fc1_b = (const float*)d_in[3];
    const float* fc2_w = (const float*)d_in[4];
    const float* fc2_b = (const float*)d_in[5];
    const float* ew    = (const float*)d_in[6];
    const float* eb    = (const float*)d_in[7];
    float*       out   = (float*)d_out;

    static bool attr_set = false;
    if (!attr_set) {
        cudaFuncSetAttribute(fc1_kernel, cudaFuncAttributeMaxDynamicSharedMemorySize, SMEM_BYTES);
        cudaFuncSetAttribute(fc2_kernel, cudaFuncAttributeMaxDynamicSharedMemorySize, SMEM_BYTES);
        attr_set = true;
    }

    prep_kernel<<<592, 256>>>(hs, fc1_w, fc2_w, ew, raw);

    dim3 g1(H_DIM / 128, M_TOT / 128);   // (24, 96)
    fc1_kernel<<<g1, 128, SMEM_BYTES>>>(fc1_b);

    fc2_kernel<<<640, 128, SMEM_BYTES>>>(fc2_b, eb, out);
}